// round 14
// baseline (speedup 1.0000x reference)
#include <cuda_runtime.h>
#include <math.h>
#include <stdint.h>

// ---------------- problem constants ----------------
#define BB   2
#define N1L  2048
#define N2L  128
#define TT   2176          // N1 + N2
#define DD   1024
#define HH   16
#define DHH  64
#define ND3  3072          // 3*D
#define NKT  34            // T/64 kv tiles
#define QTR  128           // q rows per attn block
#define NQT  17            // T/128 q tiles

// ---------------- scratch (__device__ globals; no allocs allowed) ----------------
// Packed, tf32-pre-rounded tiles for attention:
// Qp: [bh][qt(17)][kc(8)][r(128)][8]   elem (r,k): slot = 2*((k&7)&3) + ((k&7)>>2)
// Kp: [bh][kt(34)][kc(8)][r(64)][8]    same packing per 64-row tile
// Vp: [bh][kt(34)][ (kv>>3)*512 + d*8 + (kv&7) ]   pair-packed for LDS.64 b-frags
__device__ float g_qp[BB * HH * NQT * 8 * 128 * 8];
__device__ float g_kp[BB * HH * NKT * 8 * 64 * 8];
__device__ float g_vp[BB * HH * NKT * 4096];
__device__ float g_x[BB * TT * DD];               // attention output, heads merged

// ---------------- helpers ----------------
__device__ __forceinline__ float to_tf32(float x) {
    uint32_t u;
    asm("cvt.rna.tf32.f32 %0, %1;" : "=r"(u) : "f"(x));
    return __uint_as_float(u);
}

__device__ __forceinline__ void mma_tf32_v(float* c, const float a0, const float a1,
                                           const float a2, const float a3,
                                           const float b0, const float b1) {
    asm volatile(
        "mma.sync.aligned.m16n8k8.row.col.f32.tf32.tf32.f32 "
        "{%0,%1,%2,%3}, {%4,%5,%6,%7}, {%8,%9}, {%0,%1,%2,%3};"
        : "+f"(c[0]), "+f"(c[1]), "+f"(c[2]), "+f"(c[3])
        : "r"(__float_as_uint(a0)), "r"(__float_as_uint(a1)),
          "r"(__float_as_uint(a2)), "r"(__float_as_uint(a3)),
          "r"(__float_as_uint(b0)), "r"(__float_as_uint(b1)));
}

__device__ __forceinline__ void cp16(uint32_t smem_dst, const void* gsrc) {
    asm volatile("cp.async.cg.shared.global [%0], [%1], 16;\n"
                 :: "r"(smem_dst), "l"(gsrc));
}
#define CP_COMMIT() asm volatile("cp.async.commit_group;\n" ::: "memory")
#define CP_WAIT1()  asm volatile("cp.async.wait_group 1;\n" ::: "memory")

#define BLD 136
// A pair-packed buffer: Ap[ks(2)][row(128)][tig(4)] float2 -> 2048 floats/buffer.
// elem (r,k): float off = ((k>>3)*128 + r)*8 + (k&3)*2 + ((k>>2)&1)

// =====================================================================
// QKV GEMM with FUSED RMSNorm + packed scatter epilogue. Packed A frags.
// BM=128, BN=128, BK=16; grid (24, 34): y<32 -> x1 set, else x2 set.
// bn region: 0..7 = q, 8..15 = k, 16..23 = v. Each q/k block = 2 heads.
// =====================================================================
__global__ __launch_bounds__(256) void qkv_gemm_fused(
    const float* __restrict__ A1, const float* __restrict__ W1,
    const float* __restrict__ bias1,
    const float* __restrict__ A2, const float* __restrict__ W2,
    const float* __restrict__ bias2,
    const float* __restrict__ gq1, const float* __restrict__ gk1,
    const float* __restrict__ gq2, const float* __restrict__ gk2)
{
    __shared__ float Ap[2][2048];
    __shared__ float Bs[2][16 * BLD];
    __shared__ float red[128][2][2];   // [row][head-in-block][col-half]

    const int N = ND3, K = DD;
    bool s0 = (blockIdx.y < 32);
    const float* A    = s0 ? A1 : A2;
    const float* W    = s0 ? W1 : W2;
    const float* bias = s0 ? bias1 : bias2;
    int bm = s0 ? blockIdx.y : blockIdx.y - 32;

    int tid = threadIdx.x;
    int bn = blockIdx.x;
    int warp = tid >> 5, lane = tid & 31;
    int g = lane >> 2, tig = lane & 3;
    int wm = (warp >> 2) * 64, wn = (warp & 3) * 32;

    // A rows are identity for both sets
    int a_row[2], a_st[2];
    const float* a_ptr[2];
#pragma unroll
    for (int i = 0; i < 2; i++) {
        int idx = tid + i * 256;
        a_row[i] = idx >> 2;
        int kq = idx & 3;                    // k quad: k = 4*kq + j
        a_ptr[i] = A + (size_t)(bm * 128 + a_row[i]) * K + kq * 4;
        a_st[i] = ((kq >> 1) * 128 + a_row[i]) * 8 + (kq & 1);   // +2j per elem
    }
    int b_kr[2], b_nq[2];
    const float* b_ptr[2];
#pragma unroll
    for (int i = 0; i < 2; i++) {
        int idx = tid + i * 256;
        b_kr[i] = idx >> 5;
        b_nq[i] = (idx & 31) * 4;
        b_ptr[i] = W + (size_t)b_kr[i] * N + bn * 128 + b_nq[i];
    }

    float acc[4][4][4];
#pragma unroll
    for (int mt = 0; mt < 4; mt++)
#pragma unroll
        for (int nt = 0; nt < 4; nt++)
#pragma unroll
            for (int r = 0; r < 4; r++) acc[mt][nt][r] = 0.f;

    int ntiles = K >> 4;
    float4 av[2], bv[2];
#pragma unroll
    for (int i = 0; i < 2; i++) {
        av[i] = *(const float4*)(a_ptr[i]);
        bv[i] = *(const float4*)(b_ptr[i]);
    }
#pragma unroll
    for (int i = 0; i < 2; i++) {
        float* as = &Ap[0][a_st[i]];
        as[0] = to_tf32(av[i].x); as[2] = to_tf32(av[i].y);
        as[4] = to_tf32(av[i].z); as[6] = to_tf32(av[i].w);
        float* bs = &Bs[0][b_kr[i] * BLD + b_nq[i]];
        bs[0] = to_tf32(bv[i].x); bs[1] = to_tf32(bv[i].y);
        bs[2] = to_tf32(bv[i].z); bs[3] = to_tf32(bv[i].w);
    }
    __syncthreads();

    for (int t = 0; t < ntiles; t++) {
        int cur = t & 1;
        if (t + 1 < ntiles) {
            int kk = (t + 1) * 16;
#pragma unroll
            for (int i = 0; i < 2; i++) {
                av[i] = *(const float4*)(a_ptr[i] + kk);
                bv[i] = *(const float4*)(b_ptr[i] + (size_t)kk * N);
            }
        }
#pragma unroll
        for (int ks8 = 0; ks8 < 2; ks8++) {
            int ksb = ks8 * 8;
            float afr[4][4];
            float bfr[4][2];
#pragma unroll
            for (int mt = 0; mt < 4; mt++) {
                int rb = wm + mt * 16;
                float2 p0 = *(const float2*)&Ap[cur][(ks8 * 128 + rb + g)     * 8 + tig * 2];
                float2 p1 = *(const float2*)&Ap[cur][(ks8 * 128 + rb + g + 8) * 8 + tig * 2];
                afr[mt][0] = p0.x; afr[mt][1] = p1.x;
                afr[mt][2] = p0.y; afr[mt][3] = p1.y;
            }
#pragma unroll
            for (int nt = 0; nt < 4; nt++) {
                int nb = wn + nt * 8;
                bfr[nt][0] = Bs[cur][(ksb + tig)     * BLD + nb + g];
                bfr[nt][1] = Bs[cur][(ksb + tig + 4) * BLD + nb + g];
            }
#pragma unroll
            for (int mt = 0; mt < 4; mt++)
#pragma unroll
                for (int nt = 0; nt < 4; nt++)
                    mma_tf32_v(acc[mt][nt], afr[mt][0], afr[mt][1], afr[mt][2], afr[mt][3],
                               bfr[nt][0], bfr[nt][1]);
        }
        if (t + 1 < ntiles) {
            int nxt = cur ^ 1;
#pragma unroll
            for (int i = 0; i < 2; i++) {
                float* as = &Ap[nxt][a_st[i]];
                as[0] = to_tf32(av[i].x); as[2] = to_tf32(av[i].y);
                as[4] = to_tf32(av[i].z); as[6] = to_tf32(av[i].w);
                float* bs = &Bs[nxt][b_kr[i] * BLD + b_nq[i]];
                bs[0] = to_tf32(bv[i].x); bs[1] = to_tf32(bv[i].y);
                bs[2] = to_tf32(bv[i].z); bs[3] = to_tf32(bv[i].w);
            }
        }
        __syncthreads();
    }

    // ================= fused epilogue =================
#pragma unroll
    for (int nt = 0; nt < 4; nt++) {
        int cn = bn * 128 + wn + nt * 8 + 2 * tig;
        float2 bi = *(const float2*)(bias + cn);
#pragma unroll
        for (int mt = 0; mt < 4; mt++) {
            acc[mt][nt][0] += bi.x; acc[mt][nt][1] += bi.y;
            acc[mt][nt][2] += bi.x; acc[mt][nt][3] += bi.y;
        }
    }

    int region = bn >> 3;                 // 0=q, 1=k, 2=v (uniform per block)
    int hsel  = (warp & 3) >> 1;
    int part  = warp & 1;
    int head  = ((bn & 7) << 1) + hsel;
    int dbase = (warp & 1) * 32;

    if (region < 2) {
#pragma unroll
        for (int mt = 0; mt < 4; mt++) {
#pragma unroll
            for (int half = 0; half < 2; half++) {
                float ps = 0.f;
#pragma unroll
                for (int nt = 0; nt < 4; nt++) {
                    float v0 = acc[mt][nt][2 * half];
                    float v1 = acc[mt][nt][2 * half + 1];
                    ps += v0 * v0 + v1 * v1;
                }
                ps += __shfl_xor_sync(0xffffffffu, ps, 1);
                ps += __shfl_xor_sync(0xffffffffu, ps, 2);
                if (tig == 0)
                    red[wm + mt * 16 + g + 8 * half][hsel][part] = ps;
            }
        }
        __syncthreads();

        const float* gvec = (region == 0) ? (s0 ? gq1 : gq2) : (s0 ? gk1 : gk2);
        float scl = (region == 0) ? 0.125f : 1.0f;

        int e0 = 2 * tig;
        int sl0 = 2 * (e0 & 3) + (e0 >> 2);
        int sl1 = 2 * ((e0 + 1) & 3) + ((e0 + 1) >> 2);

#pragma unroll
        for (int mt = 0; mt < 4; mt++) {
#pragma unroll
            for (int half = 0; half < 2; half++) {
                int rloc = wm + mt * 16 + g + 8 * half;
                int gm = bm * 128 + rloc;
                int b, tt;
                if (s0) { b = gm >> 11; tt = gm & 2047; }
                else    { b = gm >> 7;  tt = 2048 + (gm & 127); }
                float ssum = red[rloc][hsel][0] + red[rloc][hsel][1];
                float rn = rsqrtf(ssum * (1.f / 64.f) + 1e-6f) * scl;
                int bh = b * HH + head;
#pragma unroll
                for (int nt = 0; nt < 4; nt++) {
                    int d = dbase + nt * 8 + 2 * tig;
                    float2 gv = *(const float2*)(gvec + d);
                    float v0 = to_tf32(acc[mt][nt][2 * half]     * rn * gv.x);
                    float v1 = to_tf32(acc[mt][nt][2 * half + 1] * rn * gv.y);
                    int kc = d >> 3;
                    if (region == 0) {
                        int qt = tt >> 7, r = tt & 127;
                        float* dst = g_qp + ((((size_t)bh * NQT + qt) * 8 + kc) * 128 + r) * 8;
                        dst[sl0] = v0; dst[sl1] = v1;
                    } else {
                        int kt = tt >> 6, r = tt & 63;
                        float* dst = g_kp + ((((size_t)bh * NKT + kt) * 8 + kc) * 64 + r) * 8;
                        dst[sl0] = v0; dst[sl1] = v1;
                    }
                }
            }
        }
    } else {
#pragma unroll
        for (int mt = 0; mt < 4; mt++) {
#pragma unroll
            for (int half = 0; half < 2; half++) {
                int rloc = wm + mt * 16 + g + 8 * half;
                int gm = bm * 128 + rloc;
                int b, tt;
                if (s0) { b = gm >> 11; tt = gm & 2047; }
                else    { b = gm >> 7;  tt = 2048 + (gm & 127); }
                int bh = b * HH + head;
                int kt = tt >> 6, r = tt & 63;
                float* base_v = g_vp + ((size_t)bh * NKT + kt) * 4096 + (r >> 3) * 512 + (r & 7);
#pragma unroll
                for (int nt = 0; nt < 4; nt++) {
                    int d = dbase + nt * 8 + 2 * tig;
                    base_v[d * 8]     = to_tf32(acc[mt][nt][2 * half]);
                    base_v[d * 8 + 8] = to_tf32(acc[mt][nt][2 * half + 1]);
                }
            }
        }
    }
}

// =====================================================================
// Dual-source tf32 SGEMM with packed A frags — output projections.
// =====================================================================
__global__ __launch_bounds__(256) void sgemm_tf32_dual(
    const float* __restrict__ A1, const float* __restrict__ W1,
    const float* __restrict__ bias1, float* __restrict__ C1,
    const float* __restrict__ A2, const float* __restrict__ W2,
    const float* __restrict__ bias2, float* __restrict__ C2,
    int N, int K, int split,
    int a_per1, int a_base1, int a_span1, int c_per1, int c_base1, int c_span1,
    int a_per2, int a_base2, int a_span2, int c_per2, int c_base2, int c_span2)
{
    __shared__ float Ap[2][2048];
    __shared__ float Bs[2][16 * BLD];

    bool s0 = (blockIdx.y < (unsigned)split);
    const float* A    = s0 ? A1 : A2;
    const float* W    = s0 ? W1 : W2;
    const float* bias = s0 ? bias1 : bias2;
    float* C          = s0 ? C1 : C2;
    int bm     = s0 ? blockIdx.y : blockIdx.y - split;
    int a_per  = s0 ? a_per1  : a_per2;
    int a_base = s0 ? a_base1 : a_base2;
    int a_span = s0 ? a_span1 : a_span2;
    int c_per  = s0 ? c_per1  : c_per2;
    int c_base = s0 ? c_base1 : c_base2;
    int c_span = s0 ? c_span1 : c_span2;

    int tid = threadIdx.x;
    int bn = blockIdx.x;
    int warp = tid >> 5, lane = tid & 31;
    int g = lane >> 2, tig = lane & 3;
    int wm = (warp >> 2) * 64, wn = (warp & 3) * 32;

    int a_row[2], a_st[2];
    const float* a_ptr[2];
#pragma unroll
    for (int i = 0; i < 2; i++) {
        int idx = tid + i * 256;
        a_row[i] = idx >> 2;
        int kq = idx & 3;
        int gr = bm * 128 + a_row[i];
        int arow = (gr / a_per) * a_span + a_base + (gr % a_per);
        a_ptr[i] = A + (size_t)arow * K + kq * 4;
        a_st[i] = ((kq >> 1) * 128 + a_row[i]) * 8 + (kq & 1);
    }
    int b_kr[2], b_nq[2];
    const float* b_ptr[2];
#pragma unroll
    for (int i = 0; i < 2; i++) {
        int idx = tid + i * 256;
        b_kr[i] = idx >> 5;
        b_nq[i] = (idx & 31) * 4;
        b_ptr[i] = W + (size_t)b_kr[i] * N + bn * 128 + b_nq[i];
    }

    float acc[4][4][4];
#pragma unroll
    for (int mt = 0; mt < 4; mt++)
#pragma unroll
        for (int nt = 0; nt < 4; nt++)
#pragma unroll
            for (int r = 0; r < 4; r++) acc[mt][nt][r] = 0.f;

    int ntiles = K >> 4;
    float4 av[2], bv[2];
#pragma unroll
    for (int i = 0; i < 2; i++) {
        av[i] = *(const float4*)(a_ptr[i]);
        bv[i] = *(const float4*)(b_ptr[i]);
    }
#pragma unroll
    for (int i = 0; i < 2; i++) {
        float* as = &Ap[0][a_st[i]];
        as[0] = to_tf32(av[i].x); as[2] = to_tf32(av[i].y);
        as[4] = to_tf32(av[i].z); as[6] = to_tf32(av[i].w);
        float* bs = &Bs[0][b_kr[i] * BLD + b_nq[i]];
        bs[0] = to_tf32(bv[i].x); bs[1] = to_tf32(bv[i].y);
        bs[2] = to_tf32(bv[i].z); bs[3] = to_tf32(bv[i].w);
    }
    __syncthreads();

    for (int t = 0; t < ntiles; t++) {
        int cur = t & 1;
        if (t + 1 < ntiles) {
            int kk = (t + 1) * 16;
#pragma unroll
            for (int i = 0; i < 2; i++) {
                av[i] = *(const float4*)(a_ptr[i] + kk);
                bv[i] = *(const float4*)(b_ptr[i] + (size_t)kk * N);
            }
        }
#pragma unroll
        for (int ks8 = 0; ks8 < 2; ks8++) {
            int ksb = ks8 * 8;
            float afr[4][4];
            float bfr[4][2];
#pragma unroll
            for (int mt = 0; mt < 4; mt++) {
                int rb = wm + mt * 16;
                float2 p0 = *(const float2*)&Ap[cur][(ks8 * 128 + rb + g)     * 8 + tig * 2];
                float2 p1 = *(const float2*)&Ap[cur][(ks8 * 128 + rb + g + 8) * 8 + tig * 2];
                afr[mt][0] = p0.x; afr[mt][1] = p1.x;
                afr[mt][2] = p0.y; afr[mt][3] = p1.y;
            }
#pragma unroll
            for (int nt = 0; nt < 4; nt++) {
                int nb = wn + nt * 8;
                bfr[nt][0] = Bs[cur][(ksb + tig)     * BLD + nb + g];
                bfr[nt][1] = Bs[cur][(ksb + tig + 4) * BLD + nb + g];
            }
#pragma unroll
            for (int mt = 0; mt < 4; mt++)
#pragma unroll
                for (int nt = 0; nt < 4; nt++)
                    mma_tf32_v(acc[mt][nt], afr[mt][0], afr[mt][1], afr[mt][2], afr[mt][3],
                               bfr[nt][0], bfr[nt][1]);
        }
        if (t + 1 < ntiles) {
            int nxt = cur ^ 1;
#pragma unroll
            for (int i = 0; i < 2; i++) {
                float* as = &Ap[nxt][a_st[i]];
                as[0] = to_tf32(av[i].x); as[2] = to_tf32(av[i].y);
                as[4] = to_tf32(av[i].z); as[6] = to_tf32(av[i].w);
                float* bs = &Bs[nxt][b_kr[i] * BLD + b_nq[i]];
                bs[0] = to_tf32(bv[i].x); bs[1] = to_tf32(bv[i].y);
                bs[2] = to_tf32(bv[i].z); bs[3] = to_tf32(bv[i].w);
            }
        }
        __syncthreads();
    }

#pragma unroll
    for (int mt = 0; mt < 4; mt++) {
        int gm0 = bm * 128 + wm + mt * 16 + g;
        int gm1 = gm0 + 8;
        int cr0 = (gm0 / c_per) * c_span + c_base + (gm0 % c_per);
        int cr1 = (gm1 / c_per) * c_span + c_base + (gm1 % c_per);
#pragma unroll
        for (int nt = 0; nt < 4; nt++) {
            int cn = bn * 128 + wn + nt * 8 + 2 * tig;
            float2 bi = *(const float2*)(bias + cn);
            *(float2*)(C + (size_t)cr0 * N + cn) =
                make_float2(acc[mt][nt][0] + bi.x, acc[mt][nt][1] + bi.y);
            *(float2*)(C + (size_t)cr1 * N + cn) =
                make_float2(acc[mt][nt][2] + bi.x, acc[mt][nt][3] + bi.y);
        }
    }
}

// =====================================================================
// Flash attention (unchanged from R10/R12 winner).
// =====================================================================
#define QP_F   (8 * 128 * 8)
#define KP_F   4096
#define VP_F   4096
#define KBUF_OFF(i) ((i) * 4096)
#define VBUF_OFF(i) (8192 + (i) * 4096)
#define ATTN_SMEM (16384 * 4)
__global__ __launch_bounds__(128, 2) void attn_kernel()
{
    extern __shared__ float sm[];

    int qt = blockIdx.x;
    int bh = blockIdx.y;
    int tid = threadIdx.x;
    int warp = tid >> 5, lane = tid & 31;
    int g = lane >> 2, tig = lane & 3;
    int mb = warp * 32;

    uint32_t smb = (uint32_t)__cvta_generic_to_shared(sm);

    const float* Qg = g_qp + ((size_t)bh * NQT + qt) * QP_F;
    const float* Kg = g_kp + (size_t)bh * NKT * KP_F;
    const float* Vg = g_vp + (size_t)bh * NKT * VP_F;

#pragma unroll
    for (int i = 0; i < 8; i++) {
        int c = (tid + i * 128) * 4;
        cp16(smb + (KBUF_OFF(0) + c) * 4, Kg + c);
        cp16(smb + (VBUF_OFF(0) + c) * 4, Vg + c);
    }
    CP_COMMIT();
#pragma unroll
    for (int i = 0; i < 8; i++) {
        int c = (tid + i * 128) * 4;
        cp16(smb + (KBUF_OFF(1) + c) * 4, Kg + KP_F + c);
        cp16(smb + (VBUF_OFF(1) + c) * 4, Vg + VP_F + c);
    }
    CP_COMMIT();

    float2 qf[8][4];
#pragma unroll
    for (int ks = 0; ks < 8; ks++) {
        const float* qb = Qg + ks * 1024;
        qf[ks][0] = *(const float2*)&qb[(mb + g)      * 8 + 2 * tig];
        qf[ks][1] = *(const float2*)&qb[(mb + g + 8)  * 8 + 2 * tig];
        qf[ks][2] = *(const float2*)&qb[(mb + g + 16) * 8 + 2 * tig];
        qf[ks][3] = *(const float2*)&qb[(mb + g + 24) * 8 + 2 * tig];
    }

    float S[2][8][4], O[2][8][4];
    float ls[2][2];
#pragma unroll
    for (int f = 0; f < 2; f++) {
#pragma unroll
        for (int nt = 0; nt < 8; nt++)
#pragma unroll
            for (int r = 0; r < 4; r++) O[f][nt][r] = 0.f;
        ls[f][0] = ls[f][1] = 0.f;
    }

    for (int kt = 0; kt < NKT; kt++) {
        int cur = kt & 1;
        const float* Kp = sm + KBUF_OFF(cur);
        const float* Vs = sm + VBUF_OFF(cur);

        CP_WAIT1();
        __syncthreads();

#pragma unroll
        for (int f = 0; f < 2; f++)
#pragma unroll
            for (int nt = 0; nt < 8; nt++)
#pragma unroll
                for (int r = 0; r < 4; r++) S[f][nt][r] = 0.f;
#pragma unroll
        for (int ks = 0; ks < 8; ks++) {
            const float* kb = Kp + ks * 512;
            float2 a0 = qf[ks][0], a1 = qf[ks][1];
            float2 a2 = qf[ks][2], a3 = qf[ks][3];
#pragma unroll
            for (int nt = 0; nt < 8; nt++) {
                float2 b = *(const float2*)&kb[(nt * 8 + g) * 8 + 2 * tig];
                mma_tf32_v(S[0][nt], a0.x, a1.x, a0.y, a1.y, b.x, b.y);
                mma_tf32_v(S[1][nt], a2.x, a3.x, a2.y, a3.y, b.x, b.y);
            }
        }

        float biasv = (qt < 16 && kt < 32 && (kt >> 2) > (qt >> 1)) ? 1.0f : 0.0f;

#pragma unroll
        for (int f = 0; f < 2; f++) {
            float s0 = 0.f, s1 = 0.f;
#pragma unroll
            for (int nt = 0; nt < 8; nt++) {
                float p0 = __expf(S[f][nt][0] + biasv);
                float p1 = __expf(S[f][nt][1] + biasv);
                float p2 = __expf(S[f][nt][2] + biasv);
                float p3 = __expf(S[f][nt][3] + biasv);
                S[f][nt][0] = p0; S[f][nt][1] = p1;
                S[f][nt][2] = p2; S[f][nt][3] = p3;
                s0 += p0 + p1;
                s1 += p2 + p3;
            }
            ls[f][0] += s0;
            ls[f][1] += s1;
        }

#pragma unroll
        for (int kc = 0; kc < 8; kc++) {
            const float* vb = Vs + kc * 512 + 2 * tig;
            float a00 = to_tf32(S[0][kc][0]);
            float a01 = to_tf32(S[0][kc][2]);
            float a02 = to_tf32(S[0][kc][1]);
            float a03 = to_tf32(S[0][kc][3]);
            float a10 = to_tf32(S[1][kc][0]);
            float a11 = to_tf32(S[1][kc][2]);
            float a12 = to_tf32(S[1][kc][1]);
            float a13 = to_tf32(S[1][kc][3]);
#pragma unroll
            for (int nt = 0; nt < 8; nt++) {
                float2 b = *(const float2*)&vb[(nt * 8 + g) * 8];
                mma_tf32_v(O[0][nt], a00, a01, a02, a03, b.x, b.y);
                mma_tf32_v(O[1][nt], a10, a11, a12, a13, b.x, b.y);
            }
        }

        __syncthreads();
        if (kt + 2 < NKT) {
#pragma unroll
            for (int i = 0; i < 8; i++) {
                int c = (tid + i * 128) * 4;
                cp16(smb + (KBUF_OFF(cur) + c) * 4, Kg + (size_t)(kt + 2) * KP_F + c);
                cp16(smb + (VBUF_OFF(cur) + c) * 4, Vg + (size_t)(kt + 2) * VP_F + c);
            }
        }
        CP_COMMIT();
    }

#pragma unroll
    for (int f = 0; f < 2; f++)
#pragma unroll
        for (int r = 0; r < 2; r++) {
            ls[f][r] += __shfl_xor_sync(0xffffffffu, ls[f][r], 1);
            ls[f][r] += __shfl_xor_sync(0xffffffffu, ls[f][r], 2);
        }

    int b = bh / HH, h = bh % HH;
#pragma unroll
    for (int f = 0; f < 2; f++) {
        float inv0 = 1.f / ls[f][0], inv1 = 1.f / ls[f][1];
        int t0 = qt * QTR + mb + f * 16 + g;
#pragma unroll
        for (int nt = 0; nt < 8; nt++) {
            int col = h * DHH + nt * 8 + 2 * tig;
            *(float2*)(g_x + (size_t)(b * TT + t0) * DD + col) =
                make_float2(O[f][nt][0] * inv0, O[f][nt][1] * inv0);
            *(float2*)(g_x + (size_t)(b * TT + t0 + 8) * DD + col) =
                make_float2(O[f][nt][2] * inv1, O[f][nt][3] * inv1);
        }
    }
}

// =====================================================================
// Launch
// =====================================================================
extern "C" void kernel_launch(void* const* d_in, const int* in_sizes, int n_in,
                              void* d_out, int out_size)
{
    const float* x1    = (const float*)d_in[0];
    const float* x2    = (const float*)d_in[1];
    const float* Wqkv1 = (const float*)d_in[2];
    const float* bqkv1 = (const float*)d_in[3];
    const float* Wqkv2 = (const float*)d_in[4];
    const float* bqkv2 = (const float*)d_in[5];
    const float* Wout1 = (const float*)d_in[6];
    const float* bout1 = (const float*)d_in[7];
    const float* Wout2 = (const float*)d_in[8];
    const float* bout2 = (const float*)d_in[9];
    const float* gq1   = (const float*)d_in[10];
    const float* gk1   = (const float*)d_in[11];
    const float* gq2   = (const float*)d_in[12];
    const float* gk2   = (const float*)d_in[13];
    float* out = (float*)d_out;

    float* p_x = nullptr;
    cudaGetSymbolAddress((void**)&p_x, g_x);

    // QKV GEMM + fused RMSNorm + packed scatter (x1: 32 row-tiles, x2: 2)
    qkv_gemm_fused<<<dim3(ND3 / 128, 34), 256>>>(
        x1, Wqkv1, bqkv1,
        x2, Wqkv2, bqkv2,
        gq1, gk1, gq2, gk2);

    // Attention
    cudaFuncSetAttribute(attn_kernel, cudaFuncAttributeMaxDynamicSharedMemorySize, ATTN_SMEM);
    attn_kernel<<<dim3(NQT, BB * HH), 128, ATTN_SMEM>>>();

    // Output projections (out1: 32 tiles, out2: 2 tiles, merged)
    sgemm_tf32_dual<<<dim3(DD / 128, 34), 256>>>(
        p_x, Wout1, bout1, out,
        p_x, Wout2, bout2, out + (size_t)BB * N1L * DD,
        DD, DD, 32,
        N1L, 0, TT,        BB * N1L, 0, BB * N1L,
        N2L, N1L, TT,      BB * N2L, 0, BB * N2L);
}

// round 16
// speedup vs baseline: 1.0415x; 1.0415x over previous
#include <cuda_runtime.h>
#include <math.h>
#include <stdint.h>

// ---------------- problem constants ----------------
#define BB   2
#define N1L  2048
#define N2L  128
#define TT   2176          // N1 + N2
#define DD   1024
#define HH   16
#define DHH  64
#define ND3  3072          // 3*D
#define NKT  34            // T/64 kv tiles
#define QTR  128           // q rows per attn block
#define NQT  17            // T/128 q tiles

// ---------------- scratch (__device__ globals; no allocs allowed) ----------------
__device__ float g_qp[BB * HH * NQT * 8 * 128 * 8];
__device__ float g_kp[BB * HH * NKT * 8 * 64 * 8];
__device__ float g_vp[BB * HH * NKT * 4096];
__device__ float g_x[BB * TT * DD];      // attention out (tf32-rounded), heads merged
// pre-rounded (tf32-in-fp32) operand copies
__device__ float g_x1p[BB * N1L * DD];
__device__ float g_x2p[BB * N2L * DD];
__device__ float g_w1[DD * ND3];
__device__ float g_w2[DD * ND3];
__device__ float g_wo1[DD * DD];
__device__ float g_wo2[DD * DD];

// ---------------- helpers ----------------
__device__ __forceinline__ float to_tf32(float x) {
    uint32_t u;
    asm("cvt.rna.tf32.f32 %0, %1;" : "=r"(u) : "f"(x));
    return __uint_as_float(u);
}

__device__ __forceinline__ void mma_tf32_v(float* c, const float a0, const float a1,
                                           const float a2, const float a3,
                                           const float b0, const float b1) {
    asm volatile(
        "mma.sync.aligned.m16n8k8.row.col.f32.tf32.tf32.f32 "
        "{%0,%1,%2,%3}, {%4,%5,%6,%7}, {%8,%9}, {%0,%1,%2,%3};"
        : "+f"(c[0]), "+f"(c[1]), "+f"(c[2]), "+f"(c[3])
        : "r"(__float_as_uint(a0)), "r"(__float_as_uint(a1)),
          "r"(__float_as_uint(a2)), "r"(__float_as_uint(a3)),
          "r"(__float_as_uint(b0)), "r"(__float_as_uint(b1)));
}

__device__ __forceinline__ void cp16(uint32_t smem_dst, const void* gsrc) {
    asm volatile("cp.async.cg.shared.global [%0], [%1], 16;\n"
                 :: "r"(smem_dst), "l"(gsrc));
}
#define CP_COMMIT() asm volatile("cp.async.commit_group;\n" ::: "memory")
#define CP_WAIT1()  asm volatile("cp.async.wait_group 1;\n" ::: "memory")

#define ALD 20
#define BLD 136

// =====================================================================
// Elementwise tf32 pre-round: out[i] = tf32(in[i])
// =====================================================================
__global__ __launch_bounds__(256) void tf32_round_kernel(
    const float4* __restrict__ in, float4* __restrict__ out, int n4)
{
    int i = blockIdx.x * blockDim.x + threadIdx.x;
    if (i < n4) {
        float4 v = in[i];
        out[i] = make_float4(to_tf32(v.x), to_tf32(v.y), to_tf32(v.z), to_tf32(v.w));
    }
}

// =====================================================================
// QKV GEMM (cp.async fill, pre-rounded inputs) + FUSED RMSNorm + scatter.
// BM=128, BN=128, BK=16; grid (24, 34): y<32 -> x1 set, else x2 set.
// bn region: 0..7 = q, 8..15 = k, 16..23 = v. Each q/k block = 2 heads.
// =====================================================================
__global__ __launch_bounds__(256) void qkv_gemm_fused(
    const float* __restrict__ A1, const float* __restrict__ W1,
    const float* __restrict__ bias1,
    const float* __restrict__ A2, const float* __restrict__ W2,
    const float* __restrict__ bias2,
    const float* __restrict__ gq1, const float* __restrict__ gk1,
    const float* __restrict__ gq2, const float* __restrict__ gk2)
{
    __shared__ __align__(16) float As[2][128 * ALD];
    __shared__ __align__(16) float Bs[2][16 * BLD];
    __shared__ float red[128][2][2];

    const int N = ND3, K = DD;
    bool s0 = (blockIdx.y < 32);
    const float* A    = s0 ? A1 : A2;
    const float* W    = s0 ? W1 : W2;
    const float* bias = s0 ? bias1 : bias2;
    int bm = s0 ? blockIdx.y : blockIdx.y - 32;

    int tid = threadIdx.x;
    int bn = blockIdx.x;
    int warp = tid >> 5, lane = tid & 31;
    int g = lane >> 2, tig = lane & 3;
    int wm = (warp >> 2) * 64, wn = (warp & 3) * 32;

    uint32_t as_base = (uint32_t)__cvta_generic_to_shared(&As[0][0]);
    uint32_t bs_base = (uint32_t)__cvta_generic_to_shared(&Bs[0][0]);

    // A rows identity; 2 chunks/thread
    int a_soff[2];
    const float* a_ptr[2];
#pragma unroll
    for (int i = 0; i < 2; i++) {
        int idx = tid + i * 256;
        int row = idx >> 2, kq = (idx & 3) * 4;
        a_ptr[i] = A + (size_t)(bm * 128 + row) * K + kq;
        a_soff[i] = row * ALD + kq;
    }
    int b_soff[2];
    const float* b_ptr[2];
#pragma unroll
    for (int i = 0; i < 2; i++) {
        int idx = tid + i * 256;
        int kr = idx >> 5, nq = (idx & 31) * 4;
        b_ptr[i] = W + (size_t)kr * N + bn * 128 + nq;
        b_soff[i] = kr * BLD + nq;
    }

    float acc[4][4][4];
#pragma unroll
    for (int mt = 0; mt < 4; mt++)
#pragma unroll
        for (int nt = 0; nt < 4; nt++)
#pragma unroll
            for (int r = 0; r < 4; r++) acc[mt][nt][r] = 0.f;

    const int ntiles = K >> 4;   // 64

    // prologue: tiles 0 and 1
#pragma unroll
    for (int tpre = 0; tpre < 2; tpre++) {
#pragma unroll
        for (int i = 0; i < 2; i++) {
            cp16(as_base + (tpre * 2560 + a_soff[i]) * 4, a_ptr[i] + tpre * 16);
            cp16(bs_base + (tpre * 2176 + b_soff[i]) * 4, b_ptr[i] + (size_t)tpre * 16 * N);
        }
        CP_COMMIT();
    }

    for (int t = 0; t < ntiles; t++) {
        int cur = t & 1;
        CP_WAIT1();
        __syncthreads();
#pragma unroll
        for (int ks = 0; ks < 16; ks += 8) {
            float afr[4][4], bfr[4][2];
#pragma unroll
            for (int mt = 0; mt < 4; mt++) {
                int rb = wm + mt * 16;
                afr[mt][0] = As[cur][(rb + g)     * ALD + ks + tig];
                afr[mt][1] = As[cur][(rb + g + 8) * ALD + ks + tig];
                afr[mt][2] = As[cur][(rb + g)     * ALD + ks + tig + 4];
                afr[mt][3] = As[cur][(rb + g + 8) * ALD + ks + tig + 4];
            }
#pragma unroll
            for (int nt = 0; nt < 4; nt++) {
                int nb = wn + nt * 8;
                bfr[nt][0] = Bs[cur][(ks + tig)     * BLD + nb + g];
                bfr[nt][1] = Bs[cur][(ks + tig + 4) * BLD + nb + g];
            }
#pragma unroll
            for (int mt = 0; mt < 4; mt++)
#pragma unroll
                for (int nt = 0; nt < 4; nt++)
                    mma_tf32_v(acc[mt][nt], afr[mt][0], afr[mt][1], afr[mt][2], afr[mt][3],
                               bfr[nt][0], bfr[nt][1]);
        }
        __syncthreads();
        if (t + 2 < ntiles) {
            int kk = (t + 2) * 16;
#pragma unroll
            for (int i = 0; i < 2; i++) {
                cp16(as_base + (cur * 2560 + a_soff[i]) * 4, a_ptr[i] + kk);
                cp16(bs_base + (cur * 2176 + b_soff[i]) * 4, b_ptr[i] + (size_t)kk * N);
            }
        }
        CP_COMMIT();
    }

    // ================= fused epilogue =================
#pragma unroll
    for (int nt = 0; nt < 4; nt++) {
        int cn = bn * 128 + wn + nt * 8 + 2 * tig;
        float2 bi = *(const float2*)(bias + cn);
#pragma unroll
        for (int mt = 0; mt < 4; mt++) {
            acc[mt][nt][0] += bi.x; acc[mt][nt][1] += bi.y;
            acc[mt][nt][2] += bi.x; acc[mt][nt][3] += bi.y;
        }
    }

    int region = bn >> 3;
    int hsel  = (warp & 3) >> 1;
    int part  = warp & 1;
    int head  = ((bn & 7) << 1) + hsel;
    int dbase = (warp & 1) * 32;

    if (region < 2) {
#pragma unroll
        for (int mt = 0; mt < 4; mt++) {
#pragma unroll
            for (int half = 0; half < 2; half++) {
                float ps = 0.f;
#pragma unroll
                for (int nt = 0; nt < 4; nt++) {
                    float v0 = acc[mt][nt][2 * half];
                    float v1 = acc[mt][nt][2 * half + 1];
                    ps += v0 * v0 + v1 * v1;
                }
                ps += __shfl_xor_sync(0xffffffffu, ps, 1);
                ps += __shfl_xor_sync(0xffffffffu, ps, 2);
                if (tig == 0)
                    red[wm + mt * 16 + g + 8 * half][hsel][part] = ps;
            }
        }
        __syncthreads();

        const float* gvec = (region == 0) ? (s0 ? gq1 : gq2) : (s0 ? gk1 : gk2);
        float scl = (region == 0) ? 0.125f : 1.0f;

        int e0 = 2 * tig;
        int sl0 = 2 * (e0 & 3) + (e0 >> 2);
        int sl1 = 2 * ((e0 + 1) & 3) + ((e0 + 1) >> 2);

#pragma unroll
        for (int mt = 0; mt < 4; mt++) {
#pragma unroll
            for (int half = 0; half < 2; half++) {
                int rloc = wm + mt * 16 + g + 8 * half;
                int gm = bm * 128 + rloc;
                int b, tt;
                if (s0) { b = gm >> 11; tt = gm & 2047; }
                else    { b = gm >> 7;  tt = 2048 + (gm & 127); }
                float ssum = red[rloc][hsel][0] + red[rloc][hsel][1];
                float rn = rsqrtf(ssum * (1.f / 64.f) + 1e-6f) * scl;
                int bh = b * HH + head;
#pragma unroll
                for (int nt = 0; nt < 4; nt++) {
                    int d = dbase + nt * 8 + 2 * tig;
                    float2 gv = *(const float2*)(gvec + d);
                    float v0 = to_tf32(acc[mt][nt][2 * half]     * rn * gv.x);
                    float v1 = to_tf32(acc[mt][nt][2 * half + 1] * rn * gv.y);
                    int kc = d >> 3;
                    if (region == 0) {
                        int qt = tt >> 7, r = tt & 127;
                        float* dst = g_qp + ((((size_t)bh * NQT + qt) * 8 + kc) * 128 + r) * 8;
                        dst[sl0] = v0; dst[sl1] = v1;
                    } else {
                        int kt = tt >> 6, r = tt & 63;
                        float* dst = g_kp + ((((size_t)bh * NKT + kt) * 8 + kc) * 64 + r) * 8;
                        dst[sl0] = v0; dst[sl1] = v1;
                    }
                }
            }
        }
    } else {
#pragma unroll
        for (int mt = 0; mt < 4; mt++) {
#pragma unroll
            for (int half = 0; half < 2; half++) {
                int rloc = wm + mt * 16 + g + 8 * half;
                int gm = bm * 128 + rloc;
                int b, tt;
                if (s0) { b = gm >> 11; tt = gm & 2047; }
                else    { b = gm >> 7;  tt = 2048 + (gm & 127); }
                int bh = b * HH + head;
                int kt = tt >> 6, r = tt & 63;
                float* base_v = g_vp + ((size_t)bh * NKT + kt) * 4096 + (r >> 3) * 512 + (r & 7);
#pragma unroll
                for (int nt = 0; nt < 4; nt++) {
                    int d = dbase + nt * 8 + 2 * tig;
                    base_v[d * 8]     = to_tf32(acc[mt][nt][2 * half]);
                    base_v[d * 8 + 8] = to_tf32(acc[mt][nt][2 * half + 1]);
                }
            }
        }
    }
}

// =====================================================================
// Dual-source tf32 SGEMM, cp.async fill, pre-rounded inputs. Out-proj.
// =====================================================================
__global__ __launch_bounds__(256) void sgemm_tf32_dual(
    const float* __restrict__ A1, const float* __restrict__ W1,
    const float* __restrict__ bias1, float* __restrict__ C1,
    const float* __restrict__ A2, const float* __restrict__ W2,
    const float* __restrict__ bias2, float* __restrict__ C2,
    int N, int K, int split,
    int a_per1, int a_base1, int a_span1, int c_per1, int c_base1, int c_span1,
    int a_per2, int a_base2, int a_span2, int c_per2, int c_base2, int c_span2)
{
    __shared__ __align__(16) float As[2][128 * ALD];
    __shared__ __align__(16) float Bs[2][16 * BLD];

    bool s0 = (blockIdx.y < (unsigned)split);
    const float* A    = s0 ? A1 : A2;
    const float* W    = s0 ? W1 : W2;
    const float* bias = s0 ? bias1 : bias2;
    float* C          = s0 ? C1 : C2;
    int bm     = s0 ? blockIdx.y : blockIdx.y - split;
    int a_per  = s0 ? a_per1  : a_per2;
    int a_base = s0 ? a_base1 : a_base2;
    int a_span = s0 ? a_span1 : a_span2;
    int c_per  = s0 ? c_per1  : c_per2;
    int c_base = s0 ? c_base1 : c_base2;
    int c_span = s0 ? c_span1 : c_span2;

    int tid = threadIdx.x;
    int bn = blockIdx.x;
    int warp = tid >> 5, lane = tid & 31;
    int g = lane >> 2, tig = lane & 3;
    int wm = (warp >> 2) * 64, wn = (warp & 3) * 32;

    uint32_t as_base = (uint32_t)__cvta_generic_to_shared(&As[0][0]);
    uint32_t bs_base = (uint32_t)__cvta_generic_to_shared(&Bs[0][0]);

    int a_soff[2];
    const float* a_ptr[2];
#pragma unroll
    for (int i = 0; i < 2; i++) {
        int idx = tid + i * 256;
        int row = idx >> 2, kq = (idx & 3) * 4;
        int gr = bm * 128 + row;
        int arow = (gr / a_per) * a_span + a_base + (gr % a_per);
        a_ptr[i] = A + (size_t)arow * K + kq;
        a_soff[i] = row * ALD + kq;
    }
    int b_soff[2];
    const float* b_ptr[2];
#pragma unroll
    for (int i = 0; i < 2; i++) {
        int idx = tid + i * 256;
        int kr = idx >> 5, nq = (idx & 31) * 4;
        b_ptr[i] = W + (size_t)kr * N + bn * 128 + nq;
        b_soff[i] = kr * BLD + nq;
    }

    float acc[4][4][4];
#pragma unroll
    for (int mt = 0; mt < 4; mt++)
#pragma unroll
        for (int nt = 0; nt < 4; nt++)
#pragma unroll
            for (int r = 0; r < 4; r++) acc[mt][nt][r] = 0.f;

    const int ntiles = K >> 4;

#pragma unroll
    for (int tpre = 0; tpre < 2; tpre++) {
#pragma unroll
        for (int i = 0; i < 2; i++) {
            cp16(as_base + (tpre * 2560 + a_soff[i]) * 4, a_ptr[i] + tpre * 16);
            cp16(bs_base + (tpre * 2176 + b_soff[i]) * 4, b_ptr[i] + (size_t)tpre * 16 * N);
        }
        CP_COMMIT();
    }

    for (int t = 0; t < ntiles; t++) {
        int cur = t & 1;
        CP_WAIT1();
        __syncthreads();
#pragma unroll
        for (int ks = 0; ks < 16; ks += 8) {
            float afr[4][4], bfr[4][2];
#pragma unroll
            for (int mt = 0; mt < 4; mt++) {
                int rb = wm + mt * 16;
                afr[mt][0] = As[cur][(rb + g)     * ALD + ks + tig];
                afr[mt][1] = As[cur][(rb + g + 8) * ALD + ks + tig];
                afr[mt][2] = As[cur][(rb + g)     * ALD + ks + tig + 4];
                afr[mt][3] = As[cur][(rb + g + 8) * ALD + ks + tig + 4];
            }
#pragma unroll
            for (int nt = 0; nt < 4; nt++) {
                int nb = wn + nt * 8;
                bfr[nt][0] = Bs[cur][(ks + tig)     * BLD + nb + g];
                bfr[nt][1] = Bs[cur][(ks + tig + 4) * BLD + nb + g];
            }
#pragma unroll
            for (int mt = 0; mt < 4; mt++)
#pragma unroll
                for (int nt = 0; nt < 4; nt++)
                    mma_tf32_v(acc[mt][nt], afr[mt][0], afr[mt][1], afr[mt][2], afr[mt][3],
                               bfr[nt][0], bfr[nt][1]);
        }
        __syncthreads();
        if (t + 2 < ntiles) {
            int kk = (t + 2) * 16;
#pragma unroll
            for (int i = 0; i < 2; i++) {
                cp16(as_base + (cur * 2560 + a_soff[i]) * 4, a_ptr[i] + kk);
                cp16(bs_base + (cur * 2176 + b_soff[i]) * 4, b_ptr[i] + (size_t)kk * N);
            }
        }
        CP_COMMIT();
    }

#pragma unroll
    for (int mt = 0; mt < 4; mt++) {
        int gm0 = bm * 128 + wm + mt * 16 + g;
        int gm1 = gm0 + 8;
        int cr0 = (gm0 / c_per) * c_span + c_base + (gm0 % c_per);
        int cr1 = (gm1 / c_per) * c_span + c_base + (gm1 % c_per);
#pragma unroll
        for (int nt = 0; nt < 4; nt++) {
            int cn = bn * 128 + wn + nt * 8 + 2 * tig;
            float2 bi = *(const float2*)(bias + cn);
            *(float2*)(C + (size_t)cr0 * N + cn) =
                make_float2(acc[mt][nt][0] + bi.x, acc[mt][nt][1] + bi.y);
            *(float2*)(C + (size_t)cr1 * N + cn) =
                make_float2(acc[mt][nt][2] + bi.x, acc[mt][nt][3] + bi.y);
        }
    }
}

// =====================================================================
// Flash attention (R12 winner; final store tf32-rounded).
// =====================================================================
#define QP_F   (8 * 128 * 8)
#define KP_F   4096
#define VP_F   4096
#define KBUF_OFF(i) ((i) * 4096)
#define VBUF_OFF(i) (8192 + (i) * 4096)
#define ATTN_SMEM (16384 * 4)
__global__ __launch_bounds__(128, 2) void attn_kernel()
{
    extern __shared__ float sm[];

    int qt = blockIdx.x;
    int bh = blockIdx.y;
    int tid = threadIdx.x;
    int warp = tid >> 5, lane = tid & 31;
    int g = lane >> 2, tig = lane & 3;
    int mb = warp * 32;

    uint32_t smb = (uint32_t)__cvta_generic_to_shared(sm);

    const float* Qg = g_qp + ((size_t)bh * NQT + qt) * QP_F;
    const float* Kg = g_kp + (size_t)bh * NKT * KP_F;
    const float* Vg = g_vp + (size_t)bh * NKT * VP_F;

#pragma unroll
    for (int i = 0; i < 8; i++) {
        int c = (tid + i * 128) * 4;
        cp16(smb + (KBUF_OFF(0) + c) * 4, Kg + c);
        cp16(smb + (VBUF_OFF(0) + c) * 4, Vg + c);
    }
    CP_COMMIT();
#pragma unroll
    for (int i = 0; i < 8; i++) {
        int c = (tid + i * 128) * 4;
        cp16(smb + (KBUF_OFF(1) + c) * 4, Kg + KP_F + c);
        cp16(smb + (VBUF_OFF(1) + c) * 4, Vg + VP_F + c);
    }
    CP_COMMIT();

    float2 qf[8][4];
#pragma unroll
    for (int ks = 0; ks < 8; ks++) {
        const float* qb = Qg + ks * 1024;
        qf[ks][0] = *(const float2*)&qb[(mb + g)      * 8 + 2 * tig];
        qf[ks][1] = *(const float2*)&qb[(mb + g + 8)  * 8 + 2 * tig];
        qf[ks][2] = *(const float2*)&qb[(mb + g + 16) * 8 + 2 * tig];
        qf[ks][3] = *(const float2*)&qb[(mb + g + 24) * 8 + 2 * tig];
    }

    float S[2][8][4], O[2][8][4];
    float ls[2][2];
#pragma unroll
    for (int f = 0; f < 2; f++) {
#pragma unroll
        for (int nt = 0; nt < 8; nt++)
#pragma unroll
            for (int r = 0; r < 4; r++) O[f][nt][r] = 0.f;
        ls[f][0] = ls[f][1] = 0.f;
    }

    for (int kt = 0; kt < NKT; kt++) {
        int cur = kt & 1;
        const float* Kp = sm + KBUF_OFF(cur);
        const float* Vs = sm + VBUF_OFF(cur);

        CP_WAIT1();
        __syncthreads();

#pragma unroll
        for (int f = 0; f < 2; f++)
#pragma unroll
            for (int nt = 0; nt < 8; nt++)
#pragma unroll
                for (int r = 0; r < 4; r++) S[f][nt][r] = 0.f;
#pragma unroll
        for (int ks = 0; ks < 8; ks++) {
            const float* kb = Kp + ks * 512;
            float2 a0 = qf[ks][0], a1 = qf[ks][1];
            float2 a2 = qf[ks][2], a3 = qf[ks][3];
#pragma unroll
            for (int nt = 0; nt < 8; nt++) {
                float2 b = *(const float2*)&kb[(nt * 8 + g) * 8 + 2 * tig];
                mma_tf32_v(S[0][nt], a0.x, a1.x, a0.y, a1.y, b.x, b.y);
                mma_tf32_v(S[1][nt], a2.x, a3.x, a2.y, a3.y, b.x, b.y);
            }
        }

        float biasv = (qt < 16 && kt < 32 && (kt >> 2) > (qt >> 1)) ? 1.0f : 0.0f;

#pragma unroll
        for (int f = 0; f < 2; f++) {
            float s0 = 0.f, s1 = 0.f;
#pragma unroll
            for (int nt = 0; nt < 8; nt++) {
                float p0 = __expf(S[f][nt][0] + biasv);
                float p1 = __expf(S[f][nt][1] + biasv);
                float p2 = __expf(S[f][nt][2] + biasv);
                float p3 = __expf(S[f][nt][3] + biasv);
                S[f][nt][0] = p0; S[f][nt][1] = p1;
                S[f][nt][2] = p2; S[f][nt][3] = p3;
                s0 += p0 + p1;
                s1 += p2 + p3;
            }
            ls[f][0] += s0;
            ls[f][1] += s1;
        }

#pragma unroll
        for (int kc = 0; kc < 8; kc++) {
            const float* vb = Vs + kc * 512 + 2 * tig;
            float a00 = to_tf32(S[0][kc][0]);
            float a01 = to_tf32(S[0][kc][2]);
            float a02 = to_tf32(S[0][kc][1]);
            float a03 = to_tf32(S[0][kc][3]);
            float a10 = to_tf32(S[1][kc][0]);
            float a11 = to_tf32(S[1][kc][2]);
            float a12 = to_tf32(S[1][kc][1]);
            float a13 = to_tf32(S[1][kc][3]);
#pragma unroll
            for (int nt = 0; nt < 8; nt++) {
                float2 b = *(const float2*)&vb[(nt * 8 + g) * 8];
                mma_tf32_v(O[0][nt], a00, a01, a02, a03, b.x, b.y);
                mma_tf32_v(O[1][nt], a10, a11, a12, a13, b.x, b.y);
            }
        }

        __syncthreads();
        if (kt + 2 < NKT) {
#pragma unroll
            for (int i = 0; i < 8; i++) {
                int c = (tid + i * 128) * 4;
                cp16(smb + (KBUF_OFF(cur) + c) * 4, Kg + (size_t)(kt + 2) * KP_F + c);
                cp16(smb + (VBUF_OFF(cur) + c) * 4, Vg + (size_t)(kt + 2) * VP_F + c);
            }
        }
        CP_COMMIT();
    }

#pragma unroll
    for (int f = 0; f < 2; f++)
#pragma unroll
        for (int r = 0; r < 2; r++) {
            ls[f][r] += __shfl_xor_sync(0xffffffffu, ls[f][r], 1);
            ls[f][r] += __shfl_xor_sync(0xffffffffu, ls[f][r], 2);
        }

    // write out tf32-rounded (out-proj consumes directly via cp.async)
    int b = bh / HH, h = bh % HH;
#pragma unroll
    for (int f = 0; f < 2; f++) {
        float inv0 = 1.f / ls[f][0], inv1 = 1.f / ls[f][1];
        int t0 = qt * QTR + mb + f * 16 + g;
#pragma unroll
        for (int nt = 0; nt < 8; nt++) {
            int col = h * DHH + nt * 8 + 2 * tig;
            *(float2*)(g_x + (size_t)(b * TT + t0) * DD + col) =
                make_float2(to_tf32(O[f][nt][0] * inv0), to_tf32(O[f][nt][1] * inv0));
            *(float2*)(g_x + (size_t)(b * TT + t0 + 8) * DD + col) =
                make_float2(to_tf32(O[f][nt][2] * inv1), to_tf32(O[f][nt][3] * inv1));
        }
    }
}

// =====================================================================
// Launch
// =====================================================================
extern "C" void kernel_launch(void* const* d_in, const int* in_sizes, int n_in,
                              void* d_out, int out_size)
{
    const float* x1    = (const float*)d_in[0];
    const float* x2    = (const float*)d_in[1];
    const float* Wqkv1 = (const float*)d_in[2];
    const float* bqkv1 = (const float*)d_in[3];
    const float* Wqkv2 = (const float*)d_in[4];
    const float* bqkv2 = (const float*)d_in[5];
    const float* Wout1 = (const float*)d_in[6];
    const float* bout1 = (const float*)d_in[7];
    const float* Wout2 = (const float*)d_in[8];
    const float* bout2 = (const float*)d_in[9];
    const float* gq1   = (const float*)d_in[10];
    const float* gk1   = (const float*)d_in[11];
    const float* gq2   = (const float*)d_in[12];
    const float* gk2   = (const float*)d_in[13];
    float* out = (float*)d_out;

    float *p_x, *p_x1p, *p_x2p, *p_w1, *p_w2, *p_wo1, *p_wo2;
    cudaGetSymbolAddress((void**)&p_x,   g_x);
    cudaGetSymbolAddress((void**)&p_x1p, g_x1p);
    cudaGetSymbolAddress((void**)&p_x2p, g_x2p);
    cudaGetSymbolAddress((void**)&p_w1,  g_w1);
    cudaGetSymbolAddress((void**)&p_w2,  g_w2);
    cudaGetSymbolAddress((void**)&p_wo1, g_wo1);
    cudaGetSymbolAddress((void**)&p_wo2, g_wo2);

    // ---- pre-round operands to tf32 ----
    {
        int n4;
        n4 = BB * N1L * DD / 4;
        tf32_round_kernel<<<(n4 + 255) / 256, 256>>>((const float4*)x1, (float4*)p_x1p, n4);
        n4 = DD * ND3 / 4;
        tf32_round_kernel<<<(n4 + 255) / 256, 256>>>((const float4*)Wqkv1, (float4*)p_w1, n4);
        n4 = BB * N2L * DD / 4;
        tf32_round_kernel<<<(n4 + 255) / 256, 256>>>((const float4*)x2, (float4*)p_x2p, n4);
        n4 = DD * ND3 / 4;
        tf32_round_kernel<<<(n4 + 255) / 256, 256>>>((const float4*)Wqkv2, (float4*)p_w2, n4);
        n4 = DD * DD / 4;
        tf32_round_kernel<<<(n4 + 255) / 256, 256>>>((const float4*)Wout1, (float4*)p_wo1, n4);
        tf32_round_kernel<<<(n4 + 255) / 256, 256>>>((const float4*)Wout2, (float4*)p_wo2, n4);
    }

    // ---- QKV GEMM + fused RMSNorm + packed scatter ----
    qkv_gemm_fused<<<dim3(ND3 / 128, 34), 256>>>(
        p_x1p, p_w1, bqkv1,
        p_x2p, p_w2, bqkv2,
        gq1, gk1, gq2, gk2);

    // ---- Attention ----
    cudaFuncSetAttribute(attn_kernel, cudaFuncAttributeMaxDynamicSharedMemorySize, ATTN_SMEM);
    attn_kernel<<<dim3(NQT, BB * HH), 128, ATTN_SMEM>>>();

    // ---- Output projections ----
    sgemm_tf32_dual<<<dim3(DD / 128, 34), 256>>>(
        p_x, p_wo1, bout1, out,
        p_x, p_wo2, bout2, out + (size_t)BB * N1L * DD,
        DD, DD, 32,
        N1L, 0, TT,        BB * N1L, 0, BB * N1L,
        N2L, N1L, TT,      BB * N2L, 0, BB * N2L);
}